// round 1
// baseline (speedup 1.0000x reference)
#include <cuda_runtime.h>

// Problem constants (AGTLayer: N=32768, D=512, H=8, HD=64)
#define NROWS 32768
#define DDIM  512
#define NHEADS 8
#define HDIM  64
#define LN_EPS 1e-5f

// Scratch (allocation-free rule: __device__ globals)
__device__ float g_attn[(size_t)NROWS * DDIM];
__device__ float g_fh[(size_t)NROWS * DDIM];

// ---------------------------------------------------------------------------
// Tiled SGEMM: C[M,512] = A[M,512] @ B[512,512], optional ReLU epilogue.
// BM=128, BN=128, BK=8, 256 threads, 8x8 microtile per thread.
// ---------------------------------------------------------------------------
template <bool RELU>
__global__ __launch_bounds__(256) void sgemm_512(const float* __restrict__ A,
                                                 const float* __restrict__ B,
                                                 float* __restrict__ C) {
    __shared__ float As[8][128];
    __shared__ float Bs[8][128];

    const int bm  = blockIdx.y * 128;
    const int bn  = blockIdx.x * 128;
    const int tid = threadIdx.x;

    const int tr = (tid >> 4) << 3;  // thread row offset in tile (0..120)
    const int tc = (tid & 15) << 3;  // thread col offset in tile

    // load indices
    const int ar  = tid >> 1;          // 0..127
    const int ac  = (tid & 1) * 4;     // 0 or 4
    const int br  = tid >> 5;          // 0..7
    const int bc  = (tid & 31) * 4;    // 0..124

    float acc[8][8];
#pragma unroll
    for (int i = 0; i < 8; ++i)
#pragma unroll
        for (int j = 0; j < 8; ++j) acc[i][j] = 0.0f;

    for (int k0 = 0; k0 < DDIM; k0 += 8) {
        // A tile: 128 rows x 8 cols, transposed into As[k][row]
        float4 av = *(const float4*)(A + (size_t)(bm + ar) * DDIM + k0 + ac);
        As[ac + 0][ar] = av.x;
        As[ac + 1][ar] = av.y;
        As[ac + 2][ar] = av.z;
        As[ac + 3][ar] = av.w;
        // B tile: 8 rows x 128 cols
        float4 bv = *(const float4*)(B + (size_t)(k0 + br) * DDIM + bn + bc);
        *(float4*)&Bs[br][bc] = bv;
        __syncthreads();

#pragma unroll
        for (int kk = 0; kk < 8; ++kk) {
            float a[8], b[8];
#pragma unroll
            for (int i = 0; i < 8; ++i) a[i] = As[kk][tr + i];
#pragma unroll
            for (int j = 0; j < 8; ++j) b[j] = Bs[kk][tc + j];
#pragma unroll
            for (int i = 0; i < 8; ++i)
#pragma unroll
                for (int j = 0; j < 8; ++j) acc[i][j] = fmaf(a[i], b[j], acc[i][j]);
        }
        __syncthreads();
    }

#pragma unroll
    for (int i = 0; i < 8; ++i) {
#pragma unroll
        for (int j = 0; j < 8; j += 4) {
            float4 v4;
            v4.x = acc[i][j + 0];
            v4.y = acc[i][j + 1];
            v4.z = acc[i][j + 2];
            v4.w = acc[i][j + 3];
            if (RELU) {
                v4.x = fmaxf(v4.x, 0.0f);
                v4.y = fmaxf(v4.y, 0.0f);
                v4.z = fmaxf(v4.z, 0.0f);
                v4.w = fmaxf(v4.w, 0.0f);
            }
            *(float4*)(C + (size_t)(bm + tr + i) * DDIM + bn + tc + j) = v4;
        }
    }
}

// ---------------------------------------------------------------------------
// Per-node linear attention. One block (256 threads) per node.
//   kv[d][e]   = sum_h k[h,d] * v[h,e]            (64x64)
//   ksum[d]    = sum_h k[h,d]
//   denom[hh]  = sum_d q[hh,d] * ksum[d]
//   attn[hh,e] = (sum_d q[hh,d] * kv[d][e]) / denom[hh]
// ---------------------------------------------------------------------------
__global__ __launch_bounds__(256) void attn_kernel(const float* __restrict__ q,
                                                   const float* __restrict__ k,
                                                   const float* __restrict__ v,
                                                   float* __restrict__ attn) {
    const int b   = blockIdx.x;
    const int tid = threadIdx.x;

    __shared__ float qs[DDIM];
    __shared__ float ks[DDIM];
    __shared__ float vs[DDIM];
    __shared__ float kv[HDIM][HDIM + 1];
    __shared__ float ksum[HDIM];
    __shared__ float denom[NHEADS];

    const size_t base = (size_t)b * DDIM;
    qs[tid]       = q[base + tid];
    qs[tid + 256] = q[base + tid + 256];
    ks[tid]       = k[base + tid];
    ks[tid + 256] = k[base + tid + 256];
    vs[tid]       = v[base + tid];
    vs[tid + 256] = v[base + tid + 256];
    __syncthreads();

    if (tid < HDIM) {
        float s = 0.0f;
#pragma unroll
        for (int h2 = 0; h2 < NHEADS; ++h2) s += ks[h2 * HDIM + tid];
        ksum[tid] = s;
    }

    for (int idx = tid; idx < HDIM * HDIM; idx += 256) {
        const int d = idx >> 6;
        const int e = idx & 63;
        float s = 0.0f;
#pragma unroll
        for (int h2 = 0; h2 < NHEADS; ++h2)
            s = fmaf(ks[h2 * HDIM + d], vs[h2 * HDIM + e], s);
        kv[d][e] = s;
    }
    __syncthreads();

    if (tid < NHEADS) {
        float s = 0.0f;
#pragma unroll
        for (int d = 0; d < HDIM; ++d) s = fmaf(qs[tid * HDIM + d], ksum[d], s);
        denom[tid] = s;
    }
    __syncthreads();

    for (int idx = tid; idx < DDIM; idx += 256) {
        const int hh = idx >> 6;
        const int e  = idx & 63;
        float s = 0.0f;
#pragma unroll
        for (int d = 0; d < HDIM; ++d) s = fmaf(qs[hh * HDIM + d], kv[d][e], s);
        attn[base + idx] = s / denom[hh];
    }
}

// ---------------------------------------------------------------------------
// Fused residual + LayerNorm, one warp per row (512 cols, 16 per lane).
// ---------------------------------------------------------------------------
__global__ __launch_bounds__(256) void ln_kernel(const float* __restrict__ h,
                                                 const float* __restrict__ fh,
                                                 const float* __restrict__ gamma,
                                                 const float* __restrict__ beta,
                                                 float* __restrict__ out) {
    const int row  = (blockIdx.x * blockDim.x + threadIdx.x) >> 5;
    const int lane = threadIdx.x & 31;
    if (row >= NROWS) return;

    const size_t base = (size_t)row * DDIM;
    float x[16];
    float s = 0.0f;
#pragma unroll
    for (int i = 0; i < 16; ++i) {
        const int c = lane + i * 32;
        x[i] = h[base + c] + fh[base + c];
        s += x[i];
    }
#pragma unroll
    for (int off = 16; off > 0; off >>= 1) s += __shfl_xor_sync(0xffffffffu, s, off);
    const float mu = s * (1.0f / DDIM);

    float var = 0.0f;
#pragma unroll
    for (int i = 0; i < 16; ++i) {
        const float d = x[i] - mu;
        var = fmaf(d, d, var);
    }
#pragma unroll
    for (int off = 16; off > 0; off >>= 1) var += __shfl_xor_sync(0xffffffffu, var, off);
    var *= (1.0f / DDIM);

    const float r = rsqrtf(var + LN_EPS);
#pragma unroll
    for (int i = 0; i < 16; ++i) {
        const int c = lane + i * 32;
        out[base + c] = (x[i] - mu) * r * gamma[c] + beta[c];
    }
}

// ---------------------------------------------------------------------------
// kernel_launch: inputs are (h, Wq, Wk, Wv, Wf, ln_gamma, ln_beta).
// Output is the flattened tuple (out, q, k, v): 4 * N * D floats.
// ---------------------------------------------------------------------------
extern "C" void kernel_launch(void* const* d_in, const int* in_sizes, int n_in,
                              void* d_out, int out_size) {
    const float* h     = (const float*)d_in[0];
    const float* Wq    = (const float*)d_in[1];
    const float* Wk    = (const float*)d_in[2];
    const float* Wv    = (const float*)d_in[3];
    const float* Wf    = (const float*)d_in[4];
    const float* gamma = (const float*)d_in[5];
    const float* beta  = (const float*)d_in[6];

    float* out = (float*)d_out;
    float* q   = out + (size_t)NROWS * DDIM;
    float* k   = out + 2 * (size_t)NROWS * DDIM;
    float* v   = out + 3 * (size_t)NROWS * DDIM;

    void* attn_ptr = nullptr;
    void* fh_ptr   = nullptr;
    cudaGetSymbolAddress(&attn_ptr, g_attn);
    cudaGetSymbolAddress(&fh_ptr, g_fh);

    const dim3 ggrid(DDIM / 128, NROWS / 128);  // (4, 256)

    sgemm_512<true><<<ggrid, 256>>>(h, Wq, q);
    sgemm_512<true><<<ggrid, 256>>>(h, Wk, k);
    sgemm_512<false><<<ggrid, 256>>>(h, Wv, v);

    attn_kernel<<<NROWS, 256>>>(q, k, v, (float*)attn_ptr);

    sgemm_512<false><<<ggrid, 256>>>((const float*)attn_ptr, Wf, (float*)fh_ptr);

    ln_kernel<<<(NROWS * 32) / 256, 256>>>(h, (const float*)fh_ptr, gamma, beta, out);
}

// round 2
// speedup vs baseline: 1.2784x; 1.2784x over previous
#include <cuda_runtime.h>

// Problem constants (AGTLayer: N=32768, D=512, H=8, HD=64)
#define NROWS 32768
#define DDIM  512
#define NHEADS 8
#define HDIM  64
#define LN_EPS 1e-5f

// Scratch (allocation-free rule: __device__ globals)
__device__ float g_attn[(size_t)NROWS * DDIM];
__device__ float g_fh[(size_t)NROWS * DDIM];

// ---------------------------------------------------------------------------
// Tiled SGEMM with packed f32x2 FMA: C[M,512] = A[M,512] @ B[512,512].
// BM=128, BN=128, BK=16, 256 threads, 8x8 microtile, double-buffered smem,
// one __syncthreads per K-iter. Inner product uses fma.rn.f32x2 (FFMA2).
// ---------------------------------------------------------------------------
template <bool RELU>
__global__ __launch_bounds__(256, 2) void sgemm2(const float* __restrict__ A,
                                                 const float* __restrict__ B,
                                                 float* __restrict__ C) {
    __shared__ float As[2][16][128];   // transposed: As[k][m]
    __shared__ float Bs[2][16][128];   // Bs[k][n]

    const int bm  = blockIdx.y * 128;
    const int bn  = blockIdx.x * 128;
    const int tid = threadIdx.x;

    // global-load indices
    const int ar = tid & 127;           // A row in tile
    const int ak = (tid >> 7) * 8;      // A k-offset (0 or 8), loads 8 k's
    const int br = tid >> 5;            // B row (0..7), also row br+8
    const int bc = (tid & 31) * 4;      // B col offset

    // microtile indices
    const int tr = (tid >> 4) * 8;
    const int tc = (tid & 15) * 8;

    unsigned long long acc[8][4];       // acc[i][j] = packed cols (tc+2j, tc+2j+1)
#pragma unroll
    for (int i = 0; i < 8; ++i)
#pragma unroll
        for (int j = 0; j < 4; ++j) acc[i][j] = 0ull;

    float4 a0, a1, b0, b1;

    // prologue: load tile 0
    {
        const float* Ap = A + (size_t)(bm + ar) * DDIM + ak;
        a0 = *(const float4*)Ap;
        a1 = *(const float4*)(Ap + 4);
        const float* Bp = B + (size_t)br * DDIM + bn + bc;
        b0 = *(const float4*)Bp;
        b1 = *(const float4*)(Bp + 8 * DDIM);
    }
    {
        As[0][ak + 0][ar] = a0.x; As[0][ak + 1][ar] = a0.y;
        As[0][ak + 2][ar] = a0.z; As[0][ak + 3][ar] = a0.w;
        As[0][ak + 4][ar] = a1.x; As[0][ak + 5][ar] = a1.y;
        As[0][ak + 6][ar] = a1.z; As[0][ak + 7][ar] = a1.w;
        *(float4*)&Bs[0][br][bc]     = b0;
        *(float4*)&Bs[0][br + 8][bc] = b1;
    }
    __syncthreads();

    for (int it = 0; it < DDIM / 16; ++it) {
        const int cb = it & 1;
        if (it < DDIM / 16 - 1) {
            const int k0 = (it + 1) * 16;
            const float* Ap = A + (size_t)(bm + ar) * DDIM + k0 + ak;
            a0 = *(const float4*)Ap;
            a1 = *(const float4*)(Ap + 4);
            const float* Bp = B + (size_t)(k0 + br) * DDIM + bn + bc;
            b0 = *(const float4*)Bp;
            b1 = *(const float4*)(Bp + 8 * DDIM);
        }

#pragma unroll
        for (int kk = 0; kk < 16; ++kk) {
            float4 t0 = *(const float4*)&As[cb][kk][tr];
            float4 t1 = *(const float4*)&As[cb][kk][tr + 4];
            float af[8] = {t0.x, t0.y, t0.z, t0.w, t1.x, t1.y, t1.z, t1.w};
            ulonglong2 u0 = *(const ulonglong2*)&Bs[cb][kk][tc];
            ulonglong2 u1 = *(const ulonglong2*)&Bs[cb][kk][tc + 4];
            unsigned long long b2[4] = {u0.x, u0.y, u1.x, u1.y};
#pragma unroll
            for (int i = 0; i < 8; ++i) {
                unsigned long long a2;
                asm("mov.b64 %0, {%1, %1};" : "=l"(a2) : "f"(af[i]));
#pragma unroll
                for (int j = 0; j < 4; ++j)
                    asm("fma.rn.f32x2 %0, %1, %2, %0;"
                        : "+l"(acc[i][j]) : "l"(a2), "l"(b2[j]));
            }
        }

        if (it < DDIM / 16 - 1) {
            const int nb = (it + 1) & 1;
            As[nb][ak + 0][ar] = a0.x; As[nb][ak + 1][ar] = a0.y;
            As[nb][ak + 2][ar] = a0.z; As[nb][ak + 3][ar] = a0.w;
            As[nb][ak + 4][ar] = a1.x; As[nb][ak + 5][ar] = a1.y;
            As[nb][ak + 6][ar] = a1.z; As[nb][ak + 7][ar] = a1.w;
            *(float4*)&Bs[nb][br][bc]     = b0;
            *(float4*)&Bs[nb][br + 8][bc] = b1;
            __syncthreads();
        }
    }

    // epilogue
#pragma unroll
    for (int i = 0; i < 8; ++i) {
        float o[8];
#pragma unroll
        for (int j = 0; j < 4; ++j) {
            float lo, hi;
            asm("mov.b64 {%0, %1}, %2;" : "=f"(lo), "=f"(hi) : "l"(acc[i][j]));
            o[2 * j]     = lo;
            o[2 * j + 1] = hi;
        }
        if (RELU) {
#pragma unroll
            for (int j = 0; j < 8; ++j) o[j] = fmaxf(o[j], 0.0f);
        }
        float* Cp = C + (size_t)(bm + tr + i) * DDIM + bn + tc;
        *(float4*)Cp       = make_float4(o[0], o[1], o[2], o[3]);
        *(float4*)(Cp + 4) = make_float4(o[4], o[5], o[6], o[7]);
    }
}

// ---------------------------------------------------------------------------
// Per-node linear attention, algebraically reduced via 8x8 score matrix:
//   S[h,h'] = q[h]·k[h'];  attn[h,e] = (sum_h' S[h,h'] v[h',e]) / (sum_h' S[h,h'])
// 4 nodes per 256-thread block, 64 threads per node.
// ---------------------------------------------------------------------------
#define PADR 68   // padded row stride (floats) for 64-dim head rows

__global__ __launch_bounds__(256) void attn2(const float* __restrict__ q,
                                             const float* __restrict__ k,
                                             const float* __restrict__ v,
                                             float* __restrict__ attn) {
    __shared__ float sq[4][NHEADS * PADR];
    __shared__ float sk[4][NHEADS * PADR];
    __shared__ float sv[4][NHEADS * PADR];
    __shared__ float Ss[4][NHEADS * NHEADS];

    const int tid = threadIdx.x;
    const int ln  = tid >> 6;   // local node 0..3
    const int t   = tid & 63;
    const size_t base = ((size_t)blockIdx.x * 4 + ln) * DDIM;

#pragma unroll
    for (int c = 0; c < 2; ++c) {
        const int i = t * 4 + c * 256;      // float index of float4 start
        const int h = i >> 6;
        const int d = i & 63;
        *(float4*)&sq[ln][h * PADR + d] = *(const float4*)(q + base + i);
        *(float4*)&sk[ln][h * PADR + d] = *(const float4*)(k + base + i);
        *(float4*)&sv[ln][h * PADR + d] = *(const float4*)(v + base + i);
    }
    __syncthreads();

    // score matrix: thread t computes S[h][h'], h=t>>3, h'=t&7
    {
        const float* qp = &sq[ln][(t >> 3) * PADR];
        const float* kp = &sk[ln][(t & 7) * PADR];
        float s = 0.0f;
#pragma unroll
        for (int d = 0; d < HDIM; ++d) s = fmaf(qp[d], kp[d], s);
        Ss[ln][t] = s;
    }
    __syncthreads();

    // output: thread t owns column e=t for all 8 heads
    {
        const int e = t;
#pragma unroll
        for (int h = 0; h < NHEADS; ++h) {
            float num = 0.0f, den = 0.0f;
#pragma unroll
            for (int hp = 0; hp < NHEADS; ++hp) {
                const float Sv = Ss[ln][h * NHEADS + hp];
                den += Sv;
                num = fmaf(Sv, sv[ln][hp * PADR + e], num);
            }
            attn[base + h * HDIM + e] = num / den;
        }
    }
}

// ---------------------------------------------------------------------------
// Fused residual + LayerNorm, one warp per row.
// ---------------------------------------------------------------------------
__global__ __launch_bounds__(256) void ln_kernel(const float* __restrict__ h,
                                                 const float* __restrict__ fh,
                                                 const float* __restrict__ gamma,
                                                 const float* __restrict__ beta,
                                                 float* __restrict__ out) {
    const int row  = (blockIdx.x * blockDim.x + threadIdx.x) >> 5;
    const int lane = threadIdx.x & 31;
    if (row >= NROWS) return;

    const size_t base = (size_t)row * DDIM;
    float x[16];
    float s = 0.0f;
#pragma unroll
    for (int i = 0; i < 16; ++i) {
        const int c = lane + i * 32;
        x[i] = h[base + c] + fh[base + c];
        s += x[i];
    }
#pragma unroll
    for (int off = 16; off > 0; off >>= 1) s += __shfl_xor_sync(0xffffffffu, s, off);
    const float mu = s * (1.0f / DDIM);

    float var = 0.0f;
#pragma unroll
    for (int i = 0; i < 16; ++i) {
        const float d = x[i] - mu;
        var = fmaf(d, d, var);
    }
#pragma unroll
    for (int off = 16; off > 0; off >>= 1) var += __shfl_xor_sync(0xffffffffu, var, off);
    var *= (1.0f / DDIM);

    const float r = rsqrtf(var + LN_EPS);
#pragma unroll
    for (int i = 0; i < 16; ++i) {
        const int c = lane + i * 32;
        out[base + c] = (x[i] - mu) * r * gamma[c] + beta[c];
    }
}

// ---------------------------------------------------------------------------
// kernel_launch: inputs (h, Wq, Wk, Wv, Wf, ln_gamma, ln_beta).
// Output is the flattened tuple (out, q, k, v): 4 * N * D floats.
// ---------------------------------------------------------------------------
extern "C" void kernel_launch(void* const* d_in, const int* in_sizes, int n_in,
                              void* d_out, int out_size) {
    const float* h     = (const float*)d_in[0];
    const float* Wq    = (const float*)d_in[1];
    const float* Wk    = (const float*)d_in[2];
    const float* Wv    = (const float*)d_in[3];
    const float* Wf    = (const float*)d_in[4];
    const float* gamma = (const float*)d_in[5];
    const float* beta  = (const float*)d_in[6];

    float* out = (float*)d_out;
    float* q   = out + (size_t)NROWS * DDIM;
    float* k   = out + 2 * (size_t)NROWS * DDIM;
    float* v   = out + 3 * (size_t)NROWS * DDIM;

    void* attn_ptr = nullptr;
    void* fh_ptr   = nullptr;
    cudaGetSymbolAddress(&attn_ptr, g_attn);
    cudaGetSymbolAddress(&fh_ptr, g_fh);

    const dim3 ggrid(DDIM / 128, NROWS / 128);  // (4, 256)

    sgemm2<true><<<ggrid, 256>>>(h, Wq, q);
    sgemm2<true><<<ggrid, 256>>>(h, Wk, k);
    sgemm2<false><<<ggrid, 256>>>(h, Wv, v);

    attn2<<<NROWS / 4, 256>>>(q, k, v, (float*)attn_ptr);

    sgemm2<false><<<ggrid, 256>>>((const float*)attn_ptr, Wf, (float*)fh_ptr);

    ln_kernel<<<(NROWS * 32) / 256, 256>>>(h, (const float*)fh_ptr, gamma, beta, out);
}

// round 5
// speedup vs baseline: 2.8142x; 2.2014x over previous
#include <cuda_runtime.h>
#include <cuda_fp16.h>
#include <cstdint>

// Problem constants (AGTLayer: N=32768, D=512, H=8, HD=64)
#define NROWS 32768
#define DDIM  512
#define NHEADS 8
#define HDIM  64
#define LN_EPS 1e-5f

// ---------------------------------------------------------------------------
// Scratch (__device__ globals; allocation-free rule)
// ---------------------------------------------------------------------------
__device__ __half g_h_hi[(size_t)NROWS * DDIM];
__device__ __half g_h_lo[(size_t)NROWS * DDIM];
__device__ __half g_at_hi[(size_t)NROWS * DDIM];
__device__ __half g_at_lo[(size_t)NROWS * DDIM];
__device__ __half g_wt_hi[4 * DDIM * DDIM];   // transposed: Wt[n][k]
__device__ __half g_wt_lo[4 * DDIM * DDIM];
__device__ float g_fh[(size_t)NROWS * DDIM];

// ---------------------------------------------------------------------------
// helpers
// ---------------------------------------------------------------------------
__device__ __forceinline__ uint32_t s2u(const void* p) {
    uint32_t a;
    asm("{ .reg .u64 t; cvta.to.shared.u64 t, %1; cvt.u32.u64 %0, t; }"
        : "=r"(a) : "l"(p));
    return a;
}

__device__ __forceinline__ void cpasync16(uint32_t dst, const void* src) {
    asm volatile("cp.async.cg.shared.global [%0], [%1], 16;" :: "r"(dst), "l"(src));
}
__device__ __forceinline__ void cp_commit() {
    asm volatile("cp.async.commit_group;" ::: "memory");
}
__device__ __forceinline__ void cp_wait1() {
    asm volatile("cp.async.wait_group 1;" ::: "memory");
}

__device__ __forceinline__ uint32_t lds32(uint32_t a) {
    uint32_t v;
    asm volatile("ld.shared.b32 %0, [%1];" : "=r"(v) : "r"(a));
    return v;
}

__device__ __forceinline__ void mma16816(float* c, const uint32_t* a, const uint32_t* b) {
    asm volatile(
        "mma.sync.aligned.m16n8k16.row.col.f32.f16.f16.f32 "
        "{%0,%1,%2,%3}, {%4,%5,%6,%7}, {%8,%9}, {%0,%1,%2,%3};"
        : "+f"(c[0]), "+f"(c[1]), "+f"(c[2]), "+f"(c[3])
        : "r"(a[0]), "r"(a[1]), "r"(a[2]), "r"(a[3]), "r"(b[0]), "r"(b[1]));
}

// ---------------------------------------------------------------------------
// Conversion: fp32 -> fp16 hi/lo (element-wise, vectorized)
// ---------------------------------------------------------------------------
__global__ __launch_bounds__(256) void conv_h(const float* __restrict__ src,
                                              __half* __restrict__ hi,
                                              __half* __restrict__ lo) {
    const size_t i4 = (size_t)blockIdx.x * 256 + threadIdx.x;
    float4 x = ((const float4*)src)[i4];
    float f[4] = {x.x, x.y, x.z, x.w};
    __half H[4], L[4];
#pragma unroll
    for (int i = 0; i < 4; ++i) {
        H[i] = __float2half(f[i]);
        L[i] = __float2half(f[i] - __half2float(H[i]));
    }
    __half2 h01, h23, l01, l23;
    h01.x = H[0]; h01.y = H[1]; h23.x = H[2]; h23.y = H[3];
    l01.x = L[0]; l01.y = L[1]; l23.x = L[2]; l23.y = L[3];
    ((__half2*)hi)[i4 * 2]     = h01;
    ((__half2*)hi)[i4 * 2 + 1] = h23;
    ((__half2*)lo)[i4 * 2]     = l01;
    ((__half2*)lo)[i4 * 2 + 1] = l23;
}

// ---------------------------------------------------------------------------
// Conversion + transpose: W[k][n] fp32 -> Wt[n][k] fp16 hi/lo (4 matrices)
// ---------------------------------------------------------------------------
__global__ __launch_bounds__(256) void conv_wt(const float* __restrict__ W0,
                                               const float* __restrict__ W1,
                                               const float* __restrict__ W2,
                                               const float* __restrict__ W3,
                                               __half* __restrict__ hi,
                                               __half* __restrict__ lo) {
    const float* W = (blockIdx.z == 0) ? W0 : (blockIdx.z == 1) ? W1
                     : (blockIdx.z == 2) ? W2 : W3;
    __shared__ float t[32][33];
    const int tx = threadIdx.x, ty = threadIdx.y;  // 32 x 8
    const int n0 = blockIdx.x * 32, k0 = blockIdx.y * 32;
#pragma unroll
    for (int i = 0; i < 4; ++i)
        t[ty + i * 8][tx] = W[(size_t)(k0 + ty + i * 8) * DDIM + n0 + tx];
    __syncthreads();
    const size_t base = (size_t)blockIdx.z * DDIM * DDIM;
#pragma unroll
    for (int i = 0; i < 4; ++i) {
        const int n = n0 + ty + i * 8;
        const int k = k0 + tx;
        const float v = t[tx][ty + i * 8];
        const __half hv = __float2half(v);
        hi[base + (size_t)n * DDIM + k] = hv;
        lo[base + (size_t)n * DDIM + k] = __float2half(v - __half2float(hv));
    }
}

// ---------------------------------------------------------------------------
// HMMA split-fp16 GEMM: C[M,512] fp32 = A @ Wt^T
//   A hi/lo fp16 [M][512] row-major; B (=Wt) hi/lo fp16 [512 n][512 k]
//   C = Ah*Bh^T + Ah*Bl^T + Al*Bh^T
// CTA 128x128, BK=32, 8 warps (warp tile 64x32), cp.async double buffer.
// smem tile layout: rows padded to 40 halves (80B).
// ---------------------------------------------------------------------------
#define ASTRIDE_B 80                      // bytes per padded row
#define TILE_B    (128 * ASTRIDE_B)      // 10240 B per operand tile
#define STAGE_B   (4 * TILE_B)           // Ah, Al, Bh, Bl
#define SMEM_DYN  (2 * STAGE_B)          // 81920 B (epilogue reuses: 128*132*4 = 67584)

template <bool RELU>
__global__ __launch_bounds__(256) void gemm_mma(const __half* __restrict__ Ah,
                                                const __half* __restrict__ Al,
                                                const __half* __restrict__ Bh,
                                                const __half* __restrict__ Bl,
                                                float* __restrict__ C) {
    extern __shared__ char dsm[];
    const uint32_t sb = s2u(dsm);

    const int tid  = threadIdx.x;
    const int wid  = tid >> 5;
    const int lane = tid & 31;
    const int bm   = blockIdx.y * 128;
    const int bn   = blockIdx.x * 128;

    const int wm = (wid & 1) * 64;   // warp m offset
    const int wn = (wid >> 1) * 32;  // warp n offset

    const int r4 = lane >> 2;        // 0..7
    const int c2 = (lane & 3) * 2;   // 0,2,4,6

    float acc[4][4][4];
#pragma unroll
    for (int i = 0; i < 4; ++i)
#pragma unroll
        for (int j = 0; j < 4; ++j)
#pragma unroll
            for (int r = 0; r < 4; ++r) acc[i][j][r] = 0.0f;

    // async tile loader: 4 operand tiles, 2048 16B-chunks per stage, 8/thread
    auto load_stage = [&](int stage, int kc) {
        const uint32_t s0 = sb + stage * STAGE_B;
        const __half* srcs[4] = {Ah, Al, Bh, Bl};
        const int rows[4] = {bm, bm, bn, bn};
#pragma unroll
        for (int tile = 0; tile < 4; ++tile) {
#pragma unroll
            for (int it = 0; it < 2; ++it) {
                const int ch  = tid + it * 256;     // 0..511
                const int row = ch >> 2;
                const int off = ch & 3;
                cpasync16(s0 + tile * TILE_B + row * ASTRIDE_B + off * 16,
                          srcs[tile] + (size_t)(rows[tile] + row) * DDIM + kc + off * 8);
            }
        }
    };

    load_stage(0, 0);
    cp_commit();

    for (int kt = 0; kt < 16; ++kt) {
        __syncthreads();   // prior compute done before overwriting other stage
        if (kt < 15) load_stage((kt + 1) & 1, (kt + 1) * 32);
        cp_commit();
        cp_wait1();        // stage kt ready
        __syncthreads();

        const uint32_t s0  = sb + (kt & 1) * STAGE_B;
        const uint32_t aho = s0;
        const uint32_t alo_ = s0 + TILE_B;
        const uint32_t bho = s0 + 2 * TILE_B;
        const uint32_t blo = s0 + 3 * TILE_B;

#pragma unroll
        for (int s = 0; s < 2; ++s) {
            const int kb = s * 16;
            uint32_t bh[4][2], bl[4][2];
#pragma unroll
            for (int j = 0; j < 4; ++j) {
                const uint32_t ba = (uint32_t)((wn + j * 8 + r4) * ASTRIDE_B + (kb + c2) * 2);
                bh[j][0] = lds32(bho + ba);
                bh[j][1] = lds32(bho + ba + 16);
                bl[j][0] = lds32(blo + ba);
                bl[j][1] = lds32(blo + ba + 16);
            }
#pragma unroll
            for (int i = 0; i < 4; ++i) {
                const uint32_t aa = (uint32_t)((wm + i * 16 + r4) * ASTRIDE_B + (kb + c2) * 2);
                uint32_t ah[4], al[4];
                ah[0] = lds32(aho + aa);
                ah[1] = lds32(aho + aa + 8 * ASTRIDE_B);
                ah[2] = lds32(aho + aa + 16);
                ah[3] = lds32(aho + aa + 8 * ASTRIDE_B + 16);
                al[0] = lds32(alo_ + aa);
                al[1] = lds32(alo_ + aa + 8 * ASTRIDE_B);
                al[2] = lds32(alo_ + aa + 16);
                al[3] = lds32(alo_ + aa + 8 * ASTRIDE_B + 16);
#pragma unroll
                for (int j = 0; j < 4; ++j) {
                    mma16816(acc[i][j], ah, bh[j]);
                    mma16816(acc[i][j], ah, bl[j]);
                    mma16816(acc[i][j], al, bh[j]);
                }
            }
        }
    }

    __syncthreads();

    // epilogue: acc -> padded smem -> coalesced fp32 stores
    float* Csh = (float*)dsm;   // 128 x 132
#pragma unroll
    for (int i = 0; i < 4; ++i) {
#pragma unroll
        for (int j = 0; j < 4; ++j) {
            const int row = wm + i * 16 + r4;
            const int col = wn + j * 8 + c2;
            float d0 = acc[i][j][0], d1 = acc[i][j][1];
            float d2 = acc[i][j][2], d3 = acc[i][j][3];
            if (RELU) {
                d0 = fmaxf(d0, 0.0f); d1 = fmaxf(d1, 0.0f);
                d2 = fmaxf(d2, 0.0f); d3 = fmaxf(d3, 0.0f);
            }
            *(float2*)&Csh[row * 132 + col]       = make_float2(d0, d1);
            *(float2*)&Csh[(row + 8) * 132 + col] = make_float2(d2, d3);
        }
    }
    __syncthreads();

#pragma unroll
    for (int i = 0; i < 16; ++i) {
        const int idx = tid + i * 256;   // float4 id, 0..4095
        const int r   = idx >> 5;
        const int c4  = (idx & 31) * 4;
        const float* cr = Csh + r * 132 + c4;
        *(float4*)(C + (size_t)(bm + r) * DDIM + bn + c4) =
            make_float4(cr[0], cr[1], cr[2], cr[3]);
    }
}

// ---------------------------------------------------------------------------
// Per-node linear attention via 8x8 score matrix; emits fp16 hi/lo for Wf GEMM.
// ---------------------------------------------------------------------------
#define PADR 68

__global__ __launch_bounds__(256) void attn2(const float* __restrict__ q,
                                             const float* __restrict__ k,
                                             const float* __restrict__ v,
                                             __half* __restrict__ ahi,
                                             __half* __restrict__ alo) {
    __shared__ float sq[4][NHEADS * PADR];
    __shared__ float sk[4][NHEADS * PADR];
    __shared__ float sv[4][NHEADS * PADR];
    __shared__ float Ss[4][NHEADS * NHEADS];

    const int tid = threadIdx.x;
    const int ln  = tid >> 6;
    const int t   = tid & 63;
    const size_t base = ((size_t)blockIdx.x * 4 + ln) * DDIM;

#pragma unroll
    for (int c = 0; c < 2; ++c) {
        const int i = t * 4 + c * 256;
        const int h = i >> 6;
        const int d = i & 63;
        *(float4*)&sq[ln][h * PADR + d] = *(const float4*)(q + base + i);
        *(float4*)&sk[ln][h * PADR + d] = *(const float4*)(k + base + i);
        *(float4*)&sv[ln][h * PADR + d] = *(const float4*)(v + base + i);
    }
    __syncthreads();

    {
        const float* qp = &sq[ln][(t >> 3) * PADR];
        const float* kp = &sk[ln][(t & 7) * PADR];
        float s = 0.0f;
#pragma unroll
        for (int d = 0; d < HDIM; ++d) s = fmaf(qp[d], kp[d], s);
        Ss[ln][t] = s;
    }
    __syncthreads();

    {
        const int e = t;
#pragma unroll
        for (int h = 0; h < NHEADS; ++h) {
            float num = 0.0f, den = 0.0f;
#pragma unroll
            for (int hp = 0; hp < NHEADS; ++hp) {
                const float Sv = Ss[ln][h * NHEADS + hp];
                den += Sv;
                num = fmaf(Sv, sv[ln][hp * PADR + e], num);
            }
            const float a = num / den;
            const __half hv = __float2half(a);
            ahi[base + h * HDIM + e] = hv;
            alo[base + h * HDIM + e] = __float2half(a - __half2float(hv));
        }
    }
}

// ---------------------------------------------------------------------------
// Fused residual + LayerNorm, one warp per row.
// ---------------------------------------------------------------------------
__global__ __launch_bounds__(256) void ln_kernel(const float* __restrict__ h,
                                                 const float* __restrict__ fh,
                                                 const float* __restrict__ gamma,
                                                 const float* __restrict__ beta,
                                                 float* __restrict__ out) {
    const int row  = (blockIdx.x * blockDim.x + threadIdx.x) >> 5;
    const int lane = threadIdx.x & 31;
    if (row >= NROWS) return;

    const size_t base = (size_t)row * DDIM;
    float x[16];
    float s = 0.0f;
#pragma unroll
    for (int i = 0; i < 16; ++i) {
        const int c = lane + i * 32;
        x[i] = h[base + c] + fh[base + c];
        s += x[i];
    }
#pragma unroll
    for (int off = 16; off > 0; off >>= 1) s += __shfl_xor_sync(0xffffffffu, s, off);
    const float mu = s * (1.0f / DDIM);

    float var = 0.0f;
#pragma unroll
    for (int i = 0; i < 16; ++i) {
        const float d = x[i] - mu;
        var = fmaf(d, d, var);
    }
#pragma unroll
    for (int off = 16; off > 0; off >>= 1) var += __shfl_xor_sync(0xffffffffu, var, off);
    var *= (1.0f / DDIM);

    const float r = rsqrtf(var + LN_EPS);
#pragma unroll
    for (int i = 0; i < 16; ++i) {
        const int c = lane + i * 32;
        out[base + c] = (x[i] - mu) * r * gamma[c] + beta[c];
    }
}

// ---------------------------------------------------------------------------
// kernel_launch
// ---------------------------------------------------------------------------
extern "C" void kernel_launch(void* const* d_in, const int* in_sizes, int n_in,
                              void* d_out, int out_size) {
    const float* h     = (const float*)d_in[0];
    const float* Wq    = (const float*)d_in[1];
    const float* Wk    = (const float*)d_in[2];
    const float* Wv    = (const float*)d_in[3];
    const float* Wf    = (const float*)d_in[4];
    const float* gamma = (const float*)d_in[5];
    const float* beta  = (const float*)d_in[6];

    float* out = (float*)d_out;
    float* q   = out + (size_t)NROWS * DDIM;
    float* k   = out + 2 * (size_t)NROWS * DDIM;
    float* v   = out + 3 * (size_t)NROWS * DDIM;

    void *hhi, *hlo, *athi, *atlo, *wthi, *wtlo, *fhp;
    cudaGetSymbolAddress(&hhi, g_h_hi);
    cudaGetSymbolAddress(&hlo, g_h_lo);
    cudaGetSymbolAddress(&athi, g_at_hi);
    cudaGetSymbolAddress(&atlo, g_at_lo);
    cudaGetSymbolAddress(&wthi, g_wt_hi);
    cudaGetSymbolAddress(&wtlo, g_wt_lo);
    cudaGetSymbolAddress(&fhp, g_fh);

    cudaFuncSetAttribute(gemm_mma<true>, cudaFuncAttributeMaxDynamicSharedMemorySize, SMEM_DYN);
    cudaFuncSetAttribute(gemm_mma<false>, cudaFuncAttributeMaxDynamicSharedMemorySize, SMEM_DYN);

    __half* Hhi = (__half*)hhi;
    __half* Hlo = (__half*)hlo;
    __half* WTh = (__half*)wthi;
    __half* WTl = (__half*)wtlo;

    conv_h<<<(NROWS * DDIM) / 4 / 256, 256>>>(h, Hhi, Hlo);
    conv_wt<<<dim3(16, 16, 4), dim3(32, 8)>>>(Wq, Wk, Wv, Wf, WTh, WTl);

    const dim3 ggrid(DDIM / 128, NROWS / 128);  // (4, 256)
    const size_t WSZ = (size_t)DDIM * DDIM;

    gemm_mma<true><<<ggrid, 256, SMEM_DYN>>>(Hhi, Hlo, WTh + 0 * WSZ, WTl + 0 * WSZ, q);
    gemm_mma<true><<<ggrid, 256, SMEM_DYN>>>(Hhi, Hlo, WTh + 1 * WSZ, WTl + 1 * WSZ, k);
    gemm_mma<false><<<ggrid, 256, SMEM_DYN>>>(Hhi, Hlo, WTh + 2 * WSZ, WTl + 2 * WSZ, v);

    attn2<<<NROWS / 4, 256>>>(q, k, v, (__half*)athi, (__half*)atlo);

    gemm_mma<false><<<ggrid, 256, SMEM_DYN>>>((__half*)athi, (__half*)atlo,
                                              WTh + 3 * WSZ, WTl + 3 * WSZ, (float*)fhp);

    ln_kernel<<<(NROWS * 32) / 256, 256>>>(h, (const float*)fhp, gamma, beta, out);
}